// round 5
// baseline (speedup 1.0000x reference)
#include <cuda_runtime.h>
#include <cuda_bf16.h>
#include <cstdint>

// OctonionFanoCoherence (composition-algebra form, verified rel_err ~1.9e-6):
//   ||x̂i*x̂j - x̂k||^2 = 2 - 2*dot(omul(xi,xj), xk)*inv_i*inv_j*inv_k
//   avg_error = 2 - (2/7)*sum_l dot_l ; phi = clip(-log(avg+1e-8)*exp(ls),0,10)
//
// Pipeline: per-CTA double-buffered cp.async.cg (L1 bypass). While computing
// tile t, tile t+1 streams into the other smem buffer. SoA smem layout
// (s[o*TPB + e]) -> conflict-free LDS.128, no padding.

#define TPB  96          // threads (= elements) per tile; 2 buffers fit 48KB static smem
#define ITER 8           // tiles per CTA
#define ELEM_F4 14       // 14 float4 = 56 floats per element

// ---- VERIFIED rounds 1/3/4 — verbatim, do not re-derive ----
__device__ __forceinline__ void qmul(const float* p, const float* q, float* r) {
    r[0] = p[0]*q[0] - p[1]*q[1] - p[2]*q[2] - p[3]*q[3];
    r[1] = p[0]*q[1] + p[1]*q[0] + p[2]*q[3] - p[3]*q[2];
    r[2] = p[0]*q[2] - p[1]*q[3] + p[2]*q[0] + p[3]*q[1];
    r[3] = p[0]*q[3] + p[1]*q[2] - p[2]*q[1] + p[3]*q[0];
}
__device__ __forceinline__ void omul_v(const float* x, const float* y, float* z) {
    const float* a1 = x;     const float* a2 = x + 4;
    const float* b1 = y;     const float* b2 = y + 4;
    float t1[4], t2[4];
    qmul(a1, b1, t1);
    float cb2[4] = { b2[0], -b2[1], -b2[2], -b2[3] };
    qmul(cb2, a2, t2);
    z[0] = t1[0] - t2[0]; z[1] = t1[1] - t2[1];
    z[2] = t1[2] - t2[2]; z[3] = t1[3] - t2[3];
    qmul(b2, a1, t1);
    float cb1[4] = { b1[0], -b1[1], -b1[2], -b1[3] };
    qmul(a2, cb1, t2);
    z[4] = t1[0] + t2[0]; z[5] = t1[1] + t2[1];
    z[6] = t1[2] + t2[2]; z[7] = t1[3] + t2[3];
}
// -------------------------------------------------------------

__global__ void __launch_bounds__(TPB)
oct_fano_kernel(const float* __restrict__ in,
                const float* __restrict__ log_sens,
                float* __restrict__ out,
                int B)
{
    __shared__ float4 s[2][ELEM_F4 * TPB];   // 2 * 14*96*16 = 43008 B

    const int tid = threadIdx.x;
    const float4* in4 = reinterpret_cast<const float4*>(in);

    // Loop-invariant cp.async destination offsets (SoA: [o*TPB + e])
    uint32_t dstoff[ELEM_F4];
#pragma unroll
    for (int it = 0; it < ELEM_F4; ++it) {
        int idx4 = tid + it * TPB;
        int e = idx4 / ELEM_F4;
        int o = idx4 - e * ELEM_F4;
        dstoff[it] = (uint32_t)(o * TPB + e) * 16u;
    }
    const uint32_t sbase0 = (uint32_t)__cvta_generic_to_shared(&s[0][0]);
    const uint32_t sbase1 = (uint32_t)__cvta_generic_to_shared(&s[1][0]);

    const long long firstElem = (long long)blockIdx.x * (TPB * ITER);

    // Issue loads for tile t into buffer buf (always commits a group)
    auto issue_tile = [&](int t, uint32_t sbase) {
        long long base = firstElem + (long long)t * TPB;
        int elems = (int)min((long long)TPB, (long long)B - base);
        int n4 = (elems > 0) ? elems * ELEM_F4 : 0;
        const float4* src = in4 + base * ELEM_F4;
#pragma unroll
        for (int it = 0; it < ELEM_F4; ++it) {
            int idx4 = tid + it * TPB;
            if (idx4 < n4) {
                asm volatile("cp.async.cg.shared.global [%0], [%1], 16;\n"
                             :: "r"(sbase + dstoff[it]), "l"(src + idx4) : "memory");
            }
        }
        asm volatile("cp.async.commit_group;\n" ::: "memory");
    };

    issue_tile(0, sbase0);
    const float esens = expf(__ldg(log_sens));   // hoisted scalar

#pragma unroll
    for (int t = 0; t < ITER; ++t) {
        if (t + 1 < ITER) {
            issue_tile(t + 1, ((t + 1) & 1) ? sbase1 : sbase0);
            asm volatile("cp.async.wait_group 1;\n" ::: "memory");
        } else {
            asm volatile("cp.async.wait_group 0;\n" ::: "memory");
        }
        __syncthreads();

        const long long base = firstElem + (long long)t * TPB;
        if (base + tid < B) {
            const float4* buf = (t & 1) ? &s[1][0] : &s[0][0];

            float x[56];
#pragma unroll
            for (int o = 0; o < ELEM_F4; ++o) {
                float4 v = buf[o * TPB + tid];
                x[4*o + 0] = v.x; x[4*o + 1] = v.y;
                x[4*o + 2] = v.z; x[4*o + 3] = v.w;
            }

            float inv[7];
#pragma unroll
            for (int l = 0; l < 7; ++l) {
                float acc = 0.f;
#pragma unroll
                for (int c = 0; c < 8; ++c)
                    acc = fmaf(x[l*8 + c], x[l*8 + c], acc);
                inv[l] = rsqrtf(fmaxf(acc, 1e-24f));   // == 1/max(||x||,1e-12)
            }

            float sacc = 0.f;
#pragma unroll
            for (int l = 0; l < 7; ++l) {
                const int i = l, j = (l + 1) % 7, k = (l + 3) % 7;
                float p[8];
                omul_v(&x[i*8], &x[j*8], p);
                const float* xk = &x[k*8];
                float d = 0.f;
#pragma unroll
                for (int c = 0; c < 8; ++c)
                    d = fmaf(p[c], xk[c], d);
                sacc = fmaf(d, inv[i] * inv[j] * inv[k], sacc);
            }

            float avg = fmaf(sacc, -2.0f / 7.0f, 2.0f);
            float phi = -logf(avg + 1e-8f) * esens;
            phi = fminf(fmaxf(phi, 0.0f), 10.0f);
            out[base + tid] = phi;
        }
        __syncthreads();   // all reads of this buffer done before it is refilled
    }
}

extern "C" void kernel_launch(void* const* d_in, const int* in_sizes, int n_in,
                              void* d_out, int out_size)
{
    const float* colony   = (const float*)d_in[0];   // [B, 7, 8] fp32
    const float* log_sens = (const float*)d_in[1];   // scalar fp32
    float* out = (float*)d_out;                      // [B] fp32

    int B = in_sizes[0] / 56;
    long long per_cta = (long long)TPB * ITER;
    int blocks = (int)((B + per_cta - 1) / per_cta);
    oct_fano_kernel<<<blocks, TPB>>>(colony, log_sens, out, B);
}

// round 6
// speedup vs baseline: 1.2593x; 1.2593x over previous
#include <cuda_runtime.h>
#include <cuda_bf16.h>
#include <cstdint>

// OctonionFanoCoherence (composition-algebra form, verified rel_err ~1.9e-6):
//   ||x̂i*x̂j - x̂k||^2 = 2 - 2*dot(omul(xi,xj), xk)*inv_i*inv_j*inv_k
//   avg_error = 2 - (2/7)*sum_l dot_l ; phi = clip(-log(avg+1e-8)*exp(ls),0,10)
//
// Warp-autonomous design: each warp owns 32 elements and a private 7KB smem
// slice. cp.async.cg (L1 bypass) with lane-consecutive addresses (coalesced),
// completion via wait_group + __syncwarp only — NO __syncthreads anywhere, so
// the 28 resident warps/SM desynchronize and keep DRAM continuously busy.

#define TPB      128
#define WARPS    (TPB / 32)
#define ELEM_F4  14          // 14 float4 = 56 floats per element
#define WTILE_F4 (ELEM_F4 * 32)   // 448 float4 = 7168 B per warp

// ---- VERIFIED rounds 1/3/4 — verbatim, do not re-derive ----
__device__ __forceinline__ void qmul(const float* p, const float* q, float* r) {
    r[0] = p[0]*q[0] - p[1]*q[1] - p[2]*q[2] - p[3]*q[3];
    r[1] = p[0]*q[1] + p[1]*q[0] + p[2]*q[3] - p[3]*q[2];
    r[2] = p[0]*q[2] - p[1]*q[3] + p[2]*q[0] + p[3]*q[1];
    r[3] = p[0]*q[3] + p[1]*q[2] - p[2]*q[1] + p[3]*q[0];
}
__device__ __forceinline__ void omul_v(const float* x, const float* y, float* z) {
    const float* a1 = x;     const float* a2 = x + 4;
    const float* b1 = y;     const float* b2 = y + 4;
    float t1[4], t2[4];
    qmul(a1, b1, t1);
    float cb2[4] = { b2[0], -b2[1], -b2[2], -b2[3] };
    qmul(cb2, a2, t2);
    z[0] = t1[0] - t2[0]; z[1] = t1[1] - t2[1];
    z[2] = t1[2] - t2[2]; z[3] = t1[3] - t2[3];
    qmul(b2, a1, t1);
    float cb1[4] = { b1[0], -b1[1], -b1[2], -b1[3] };
    qmul(a2, cb1, t2);
    z[4] = t1[0] + t2[0]; z[5] = t1[1] + t2[1];
    z[6] = t1[2] + t2[2]; z[7] = t1[3] + t2[3];
}
// -------------------------------------------------------------

__global__ void __launch_bounds__(TPB)
oct_fano_kernel(const float* __restrict__ in,
                const float* __restrict__ log_sens,
                float* __restrict__ out,
                int B)
{
    __shared__ float4 s[WARPS][WTILE_F4];   // 4 * 7168 B = 28672 B

    const int lane = threadIdx.x & 31;
    const int wid  = threadIdx.x >> 5;
    const long long warpBase =
        ((long long)blockIdx.x * WARPS + wid) * 32;   // first element of this warp

    const float esens = expf(__ldg(log_sens));        // hoisted, overlaps loads

    // ---- Stage 1: warp-coalesced cp.async.cg into SoA smem slice ----
    // lane-consecutive float4 indices: idx4 = lane + 32*it  (448 per warp)
    const int elems = (int)min(32LL, (long long)B - warpBase);
    if (elems <= 0) return;
    const int n4 = elems * ELEM_F4;
    const float4* src = reinterpret_cast<const float4*>(in) + warpBase * ELEM_F4;
    const uint32_t sbase = (uint32_t)__cvta_generic_to_shared(&s[wid][0]);
#pragma unroll
    for (int it = 0; it < ELEM_F4; ++it) {
        int idx4 = lane + it * 32;
        int e = idx4 / ELEM_F4;               // const-div -> mul/shift
        int o = idx4 - e * ELEM_F4;
        uint32_t dst = sbase + (uint32_t)(o * 32 + e) * 16u;  // SoA: [o][e]
        if (idx4 < n4) {
            asm volatile("cp.async.cg.shared.global [%0], [%1], 16;\n"
                         :: "r"(dst), "l"(src + idx4) : "memory");
        }
    }
    asm volatile("cp.async.commit_group;\n" ::: "memory");
    asm volatile("cp.async.wait_group 0;\n" ::: "memory");
    __syncwarp();   // make other lanes' cp.async writes visible to this lane

    if (lane >= elems) return;

    // ---- Stage 2: per-thread compute; SoA reads are conflict-free ----
    float x[56];
    const float4* buf = &s[wid][0];
#pragma unroll
    for (int o = 0; o < ELEM_F4; ++o) {
        float4 v = buf[o * 32 + lane];
        x[4*o + 0] = v.x; x[4*o + 1] = v.y;
        x[4*o + 2] = v.z; x[4*o + 3] = v.w;
    }

    float inv[7];
#pragma unroll
    for (int l = 0; l < 7; ++l) {
        float acc = 0.f;
#pragma unroll
        for (int c = 0; c < 8; ++c)
            acc = fmaf(x[l*8 + c], x[l*8 + c], acc);
        inv[l] = rsqrtf(fmaxf(acc, 1e-24f));   // == 1/max(||x||,1e-12)
    }

    float sacc = 0.f;
#pragma unroll
    for (int l = 0; l < 7; ++l) {
        const int i = l, j = (l + 1) % 7, k = (l + 3) % 7;
        float p[8];
        omul_v(&x[i*8], &x[j*8], p);
        const float* xk = &x[k*8];
        float d = 0.f;
#pragma unroll
        for (int c = 0; c < 8; ++c)
            d = fmaf(p[c], xk[c], d);
        sacc = fmaf(d, inv[i] * inv[j] * inv[k], sacc);
    }

    float avg = fmaf(sacc, -2.0f / 7.0f, 2.0f);    // avg_error = 2 - (2/7)*s
    float phi = -logf(avg + 1e-8f) * esens;
    phi = fminf(fmaxf(phi, 0.0f), 10.0f);
    out[warpBase + lane] = phi;
}

extern "C" void kernel_launch(void* const* d_in, const int* in_sizes, int n_in,
                              void* d_out, int out_size)
{
    const float* colony   = (const float*)d_in[0];   // [B, 7, 8] fp32
    const float* log_sens = (const float*)d_in[1];   // scalar fp32
    float* out = (float*)d_out;                      // [B] fp32

    int B = in_sizes[0] / 56;
    long long per_cta = 32LL * WARPS;
    int blocks = (int)((B + per_cta - 1) / per_cta);
    oct_fano_kernel<<<blocks, TPB>>>(colony, log_sens, out, B);
}

// round 7
// speedup vs baseline: 2.2156x; 1.7594x over previous
#include <cuda_runtime.h>
#include <cuda_bf16.h>
#include <cstdint>

// OctonionFanoCoherence (composition-algebra form, verified rel_err ~1.9e-6):
//   ||x̂i*x̂j - x̂k||^2 = 2 - 2*dot(omul(xi,xj), xk)*inv_i*inv_j*inv_k
//   avg_error = 2 - (2/7)*sum_l dot_l ; phi = clip(-log(avg+1e-8)*exp(ls),0,10)
//
// Warp-autonomous, conflict-free staging:
//   each warp owns 32 elements + a 7168B smem slice in NATURAL AoS order:
//   cp.async dst slot == linear idx4 -> consecutive lanes write consecutive
//   16B slots (zero bank conflicts, zero index math). Completion via
//   wait_group + __syncwarp only; no __syncthreads, warps free-run.
//   Read side: lane*14+i float4 (2-way conflict, negligible).

#define TPB      128
#define WARPS    (TPB / 32)
#define ELEM_F4  14                 // 14 float4 = 56 floats per element
#define WTILE_F4 (ELEM_F4 * 32)     // 448 float4 = 7168 B per warp slice

// ---- VERIFIED rounds 1/3/4 — verbatim, do not re-derive ----
__device__ __forceinline__ void qmul(const float* p, const float* q, float* r) {
    r[0] = p[0]*q[0] - p[1]*q[1] - p[2]*q[2] - p[3]*q[3];
    r[1] = p[0]*q[1] + p[1]*q[0] + p[2]*q[3] - p[3]*q[2];
    r[2] = p[0]*q[2] - p[1]*q[3] + p[2]*q[0] + p[3]*q[1];
    r[3] = p[0]*q[3] + p[1]*q[2] - p[2]*q[1] + p[3]*q[0];
}
__device__ __forceinline__ void omul_v(const float* x, const float* y, float* z) {
    const float* a1 = x;     const float* a2 = x + 4;
    const float* b1 = y;     const float* b2 = y + 4;
    float t1[4], t2[4];
    qmul(a1, b1, t1);
    float cb2[4] = { b2[0], -b2[1], -b2[2], -b2[3] };
    qmul(cb2, a2, t2);
    z[0] = t1[0] - t2[0]; z[1] = t1[1] - t2[1];
    z[2] = t1[2] - t2[2]; z[3] = t1[3] - t2[3];
    qmul(b2, a1, t1);
    float cb1[4] = { b1[0], -b1[1], -b1[2], -b1[3] };
    qmul(a2, cb1, t2);
    z[4] = t1[0] + t2[0]; z[5] = t1[1] + t2[1];
    z[6] = t1[2] + t2[2]; z[7] = t1[3] + t2[3];
}
// -------------------------------------------------------------

__global__ void __launch_bounds__(TPB)
oct_fano_kernel(const float* __restrict__ in,
                const float* __restrict__ log_sens,
                float* __restrict__ out,
                int B)
{
    __shared__ float4 s[WARPS][WTILE_F4];   // 4 * 7168 = 28672 B -> 8 CTAs/SM

    const int lane = threadIdx.x & 31;
    const int wid  = threadIdx.x >> 5;
    const long long warpBase =
        ((long long)blockIdx.x * WARPS + wid) * 32;   // first element of this warp

    const float esens = expf(__ldg(log_sens));        // MUFU, overlaps loads

    const int elems = (int)min(32LL, (long long)B - warpBase);
    if (elems <= 0) return;
    const int n4 = elems * ELEM_F4;

    // ---- Stage 1: warp-coalesced cp.async.cg, NATURAL-ORDER dst ----
    // idx4 = lane + 32*it ; dst slot = idx4 (consecutive lanes -> consecutive
    // 16B smem slots: conflict-free writes, no index arithmetic).
    const float4* src = reinterpret_cast<const float4*>(in) + warpBase * ELEM_F4;
    const uint32_t sbase = (uint32_t)__cvta_generic_to_shared(&s[wid][0]);
#pragma unroll
    for (int it = 0; it < ELEM_F4; ++it) {
        int idx4 = lane + it * 32;
        if (idx4 < n4) {
            asm volatile("cp.async.cg.shared.global [%0], [%1], 16;\n"
                         :: "r"(sbase + (uint32_t)idx4 * 16u), "l"(src + idx4)
                         : "memory");
        }
    }
    asm volatile("cp.async.commit_group;\n" ::: "memory");
    asm volatile("cp.async.wait_group 0;\n" ::: "memory");
    __syncwarp();   // order other lanes' cp.async fills before our reads

    if (lane >= elems) return;

    // ---- Stage 2: per-thread compute (AoS read: slot = lane*14 + i) ----
    float x[56];
    const float4* buf = &s[wid][lane * ELEM_F4];
#pragma unroll
    for (int i = 0; i < ELEM_F4; ++i) {
        float4 v = buf[i];
        x[4*i + 0] = v.x; x[4*i + 1] = v.y;
        x[4*i + 2] = v.z; x[4*i + 3] = v.w;
    }

    float inv[7];
#pragma unroll
    for (int l = 0; l < 7; ++l) {
        float acc = 0.f;
#pragma unroll
        for (int c = 0; c < 8; ++c)
            acc = fmaf(x[l*8 + c], x[l*8 + c], acc);
        inv[l] = rsqrtf(fmaxf(acc, 1e-24f));   // == 1/max(||x||,1e-12)
    }

    float sacc = 0.f;
#pragma unroll
    for (int l = 0; l < 7; ++l) {
        const int i = l, j = (l + 1) % 7, k = (l + 3) % 7;
        float p[8];
        omul_v(&x[i*8], &x[j*8], p);
        const float* xk = &x[k*8];
        float d = 0.f;
#pragma unroll
        for (int c = 0; c < 8; ++c)
            d = fmaf(p[c], xk[c], d);
        sacc = fmaf(d, inv[i] * inv[j] * inv[k], sacc);
    }

    float avg = fmaf(sacc, -2.0f / 7.0f, 2.0f);    // avg_error = 2 - (2/7)*s
    float phi = -logf(avg + 1e-8f) * esens;
    phi = fminf(fmaxf(phi, 0.0f), 10.0f);
    out[warpBase + lane] = phi;
}

extern "C" void kernel_launch(void* const* d_in, const int* in_sizes, int n_in,
                              void* d_out, int out_size)
{
    const float* colony   = (const float*)d_in[0];   // [B, 7, 8] fp32
    const float* log_sens = (const float*)d_in[1];   // scalar fp32
    float* out = (float*)d_out;                      // [B] fp32

    int B = in_sizes[0] / 56;
    long long per_cta = 32LL * WARPS;
    int blocks = (int)((B + per_cta - 1) / per_cta);
    oct_fano_kernel<<<blocks, TPB>>>(colony, log_sens, out, B);
}